// round 6
// baseline (speedup 1.0000x reference)
#include <cuda_runtime.h>
#include <math.h>

// ---------------- problem constants ----------------
#define BSZ    4
#define CIN    3
#define IMG    224
#define PATCH  16
#define DMODEL 384
#define DEPTH  4
#define NHEAD  8
#define HD     48
#define MLPD   1536
#define NCLS   5
#define TSTEPS 25
#define NTOK   196
#define ROWS   (BSZ*NTOK) // 784
#define HP     14
#define BETAF  0.9f
#define EPSF   1e-5f
#define SCALEF 0.14433756729740643f  // 48^-0.5
#define NCHUNK 28                     // 196 = 7*28

// ---------------- device state ----------------
__device__ float g_h   [ROWS*DMODEL];
__device__ float g_y   [ROWS*DMODEL];
__device__ float g_xn  [ROWS*DMODEL];
__device__ float g_q   [ROWS*DMODEL];
__device__ float g_k   [ROWS*DMODEL];
__device__ float g_v   [ROWS*DMODEL];
__device__ float g_o   [ROWS*DMODEL];
__device__ float g_s1  [ROWS*MLPD];
__device__ float g_pool[BSZ*DMODEL];
__device__ float g_mpe [ROWS*DMODEL];
__device__ float g_mq  [DEPTH*ROWS*DMODEL];
__device__ float g_mk  [DEPTH*ROWS*DMODEL];
__device__ float g_mv  [DEPTH*ROWS*DMODEL];
__device__ float g_m1  [DEPTH*ROWS*MLPD];
__device__ float g_m2  [DEPTH*ROWS*DMODEL];
__device__ float g_mh  [BSZ*NCLS];
__device__ float g_acc [BSZ*NCLS];

// software grid barrier state
__device__ unsigned g_arrive;
__device__ unsigned g_gen;

__device__ __forceinline__ void gsync()
{
    __syncthreads();
    if (threadIdx.x == 0) {
        __threadfence();
        unsigned gen = *(volatile unsigned*)&g_gen;
        unsigned nb = gridDim.x;
        if (atomicAdd(&g_arrive, 1u) == nb - 1u) {
            g_arrive = 0u;
            __threadfence();
            *(volatile unsigned*)&g_gen = gen + 1u;
        } else {
            while (*(volatile unsigned*)&g_gen == gen) { __nanosleep(64); }
        }
    }
    __syncthreads();
}

// ---------------- shared memory union ----------------
struct SmemU {
    union {
        float patch[CIN*PATCH*PATCH];                       // conv: 3072 B
        struct { float As[16][32]; float Bs[16][32]; } g;   // gemm: 4096 B
        struct {
            unsigned long long qcb[NCHUNK];
            unsigned long long kbv[NTOK];
            unsigned long long vbv[NTOK];
            unsigned char at[NCHUNK][NTOK];
        } a;                                                // attn: ~8.9 KB
    };
};

// ---------------- gemm 32x32 tile, serial-k FMA chain per output ----------------
// MODE 0: LIF -> spike   MODE 1: yout += acc   MODE 2: LIF -> yout += spike
template<int MODE>
__device__ __forceinline__ void gemm_tile32(SmemU* sm,
        const float* __restrict__ A, const float* __restrict__ W,
        int N, int K, int bm, int bn,
        const float* __restrict__ scale, const float* __restrict__ bias,
        float* __restrict__ mem, float* __restrict__ spk, float* __restrict__ yout)
{
    const int tid = threadIdx.x;           // 256
    const int tx = tid & 15, ty = tid >> 4;
    const int lr = tid >> 3;               // 0..31
    const int lk = (tid & 7) << 1;         // 0..14 even
    float a00 = 0.f, a01 = 0.f, a10 = 0.f, a11 = 0.f;

    for (int k0 = 0; k0 < K; k0 += 16) {
        int ar = bm + lr;
        float2 av = make_float2(0.f, 0.f);
        if (ar < ROWS) av = *reinterpret_cast<const float2*>(A + (size_t)ar*K + k0 + lk);
        sm->g.As[lk][lr] = av.x; sm->g.As[lk+1][lr] = av.y;
        float2 bv = *reinterpret_cast<const float2*>(W + (size_t)(bn+lr)*K + k0 + lk);
        sm->g.Bs[lk][lr] = bv.x; sm->g.Bs[lk+1][lr] = bv.y;
        __syncthreads();
        #pragma unroll
        for (int kk = 0; kk < 16; kk++) {   // strictly ascending k
            float2 a = *reinterpret_cast<const float2*>(&sm->g.As[kk][ty*2]);
            float2 b = *reinterpret_cast<const float2*>(&sm->g.Bs[kk][tx*2]);
            a00 = __fmaf_rn(a.x, b.x, a00); a01 = __fmaf_rn(a.x, b.y, a01);
            a10 = __fmaf_rn(a.y, b.x, a10); a11 = __fmaf_rn(a.y, b.y, a11);
        }
        __syncthreads();
    }
    float accv[2][2] = {{a00, a01}, {a10, a11}};
    #pragma unroll
    for (int i = 0; i < 2; i++) {
        int m = bm + ty*2 + i;
        if (m >= ROWS) break;
        #pragma unroll
        for (int j = 0; j < 2; j++) {
            int n = bn + tx*2 + j;
            size_t idx = (size_t)m*N + n;
            float vv = accv[i][j];
            if (MODE == 1) {
                yout[idx] = __fadd_rn(yout[idx], vv);
            } else {
                vv = __fadd_rn(__fmul_rn(vv, scale[n]), bias[n]);
                float mm = __fadd_rn(__fmul_rn(BETAF, mem[idx]), vv);
                float s = (mm > 1.0f) ? 1.0f : 0.0f;
                mem[idx] = __fadd_rn(mm, -s);
                if (MODE == 0) spk[idx] = s;
                else           yout[idx] = __fadd_rn(yout[idx], s);
            }
        }
    }
}

// ---------------- layernorm row, XLA:CPU vectorized-reduce order ----------------
// 4-lane sharded strided sums (lane i: sum of x[4t+i], t ascending) then
// pairwise halving combine: (a0+a2)+(a1+a3). Warp per row.
__device__ __forceinline__ void ln_row_warp(const float* __restrict__ rin,
        const float* __restrict__ g, const float* __restrict__ bta, float* __restrict__ out)
{
    const unsigned fm = 0xffffffffu;
    int lane = threadIdx.x & 31;
    float a = 0.f;
    if (lane < 4) {
        for (int t2 = 0; t2 < 96; t2++) a = __fadd_rn(a, rin[4*t2 + lane]);
    }
    float a0 = __shfl_sync(fm, a, 0), a1 = __shfl_sync(fm, a, 1);
    float a2 = __shfl_sync(fm, a, 2), a3 = __shfl_sync(fm, a, 3);
    float mean = __fdiv_rn(__fadd_rn(__fadd_rn(a0, a2), __fadd_rn(a1, a3)), 384.0f);

    float b = 0.f;
    if (lane < 4) {
        for (int t2 = 0; t2 < 96; t2++) {
            float d = __fadd_rn(rin[4*t2 + lane], -mean);
            b = __fadd_rn(b, __fmul_rn(d, d));
        }
    }
    float b0 = __shfl_sync(fm, b, 0), b1 = __shfl_sync(fm, b, 1);
    float b2 = __shfl_sync(fm, b, 2), b3 = __shfl_sync(fm, b, 3);
    float var = __fdiv_rn(__fadd_rn(__fadd_rn(b0, b2), __fadd_rn(b1, b3)), 384.0f);
    float inv = __fdiv_rn(1.0f, __fsqrt_rn(__fadd_rn(var, EPSF)));

    for (int d = lane; d < DMODEL; d += 32) {
        float dv = __fadd_rn(rin[d], -mean);
        out[d] = __fadd_rn(__fmul_rn(__fmul_rn(dv, inv), g[d]), bta[d]);
    }
}

// ---------------- zero helper ----------------
__device__ __forceinline__ void zero_arr(float* p, int n, int gtid, int nth)
{
    for (int i = gtid; i < n; i += nth) p[i] = 0.f;
}

// ---------------- the megakernel ----------------
__global__ void __launch_bounds__(256, 3) mega(
    const float* __restrict__ x,      const float* __restrict__ conv_w,
    const float* __restrict__ bn0_s,  const float* __restrict__ bn0_b,
    const float* __restrict__ pos,
    const float* __restrict__ Wq,     const float* __restrict__ bnq_s, const float* __restrict__ bnq_b,
    const float* __restrict__ Wk,     const float* __restrict__ bnk_s, const float* __restrict__ bnk_b,
    const float* __restrict__ Wv,     const float* __restrict__ bnv_s, const float* __restrict__ bnv_b,
    const float* __restrict__ Wo,
    const float* __restrict__ ln1_g,  const float* __restrict__ ln1_b,
    const float* __restrict__ W1,     const float* __restrict__ bn1_s, const float* __restrict__ bn1_b,
    const float* __restrict__ W2,     const float* __restrict__ bn2_s, const float* __restrict__ bn2_b,
    const float* __restrict__ ln2_g,  const float* __restrict__ ln2_b,
    const float* __restrict__ lnf_g,  const float* __restrict__ lnf_b,
    const float* __restrict__ head_w, const float* __restrict__ head_b,
    float* __restrict__ out)
{
    __shared__ SmemU sm;
    const int nb  = gridDim.x;
    const int tid = threadIdx.x;
    const int wrp = tid >> 5;
    const int gtid = blockIdx.x * 256 + tid;
    const int nth  = nb * 256;

    // ---- stage: zero persistent state ----
    zero_arr(g_mpe, ROWS*DMODEL, gtid, nth);
    zero_arr(g_mq,  DEPTH*ROWS*DMODEL, gtid, nth);
    zero_arr(g_mk,  DEPTH*ROWS*DMODEL, gtid, nth);
    zero_arr(g_mv,  DEPTH*ROWS*DMODEL, gtid, nth);
    zero_arr(g_m1,  DEPTH*ROWS*MLPD, gtid, nth);
    zero_arr(g_m2,  DEPTH*ROWS*DMODEL, gtid, nth);
    zero_arr(g_mh,  BSZ*NCLS, gtid, nth);
    zero_arr(g_acc, BSZ*NCLS, gtid, nth);

    // ---- stage: conv patch embed (timestep-invariant); Eigen tap order (kh, kw, c), c minor ----
    for (int item = blockIdx.x; item < ROWS; item += nb) {
        int b = item / NTOK, n = item % NTOK;
        int py = n / HP, px = n % HP;
        for (int idx = tid; idx < 768; idx += 256) {
            int c = idx >> 8; int rem = idx & 255; int i = rem >> 4; int j = rem & 15;
            sm.patch[idx] = x[(((size_t)b*CIN + c)*IMG + (py*PATCH + i))*IMG + (px*PATCH + j)];
        }
        __syncthreads();
        for (int d = tid; d < DMODEL; d += 256) {
            const float* wr = conv_w + (size_t)d*768;
            float acc = 0.f;
            for (int i = 0; i < PATCH; i++)
                for (int j = 0; j < PATCH; j++)
                    #pragma unroll
                    for (int c = 0; c < CIN; c++) {
                        int off = c*256 + i*16 + j;
                        acc = __fmaf_rn(sm.patch[off], wr[off], acc);
                    }
            g_h[((size_t)b*NTOK + n)*DMODEL + d] = __fadd_rn(__fmul_rn(acc, bn0_s[d]), bn0_b[d]);
        }
        __syncthreads();
    }
    gsync();

    // ---- timestep loop ----
    for (int t = 0; t < TSTEPS; t++) {
        // patch-embed LIF + pos
        for (int i = gtid; i < ROWS*DMODEL; i += nth) {
            float mm = __fadd_rn(__fmul_rn(BETAF, g_mpe[i]), g_h[i]);
            float s = (mm > 1.0f) ? 1.0f : 0.0f;
            g_mpe[i] = __fadd_rn(mm, -s);
            g_y[i] = __fadd_rn(s, pos[i % (NTOK*DMODEL)]);
        }
        gsync();

        for (int l = 0; l < DEPTH; l++) {
            const size_t wOff  = (size_t)l * DMODEL * DMODEL;
            const size_t w1Off = (size_t)l * MLPD * DMODEL;
            const size_t memD  = (size_t)l * ROWS * DMODEL;
            const size_t memM  = (size_t)l * ROWS * MLPD;
            const float* Wq_l = Wq + wOff;   const float* Wk_l = Wk + wOff;
            const float* Wv_l = Wv + wOff;   const float* Wo_l = Wo + wOff;
            const float* W1_l = W1 + w1Off;  const float* W2_l = W2 + w1Off;
            const float* qs = bnq_s + l*DMODEL, *qb2 = bnq_b + l*DMODEL;
            const float* ks = bnk_s + l*DMODEL, *kb2 = bnk_b + l*DMODEL;
            const float* vs = bnv_s + l*DMODEL, *vb2 = bnv_b + l*DMODEL;
            const float* m1s = bn1_s + l*MLPD,  *m1b = bn1_b + l*MLPD;
            const float* m2s = bn2_s + l*DMODEL, *m2b = bn2_b + l*DMODEL;

            // LN1 (warp per row)
            for (int row = blockIdx.x*8 + wrp; row < ROWS; row += nb*8)
                ln_row_warp(g_y + (size_t)row*DMODEL, ln1_g + l*DMODEL, ln1_b + l*DMODEL,
                            g_xn + (size_t)row*DMODEL);
            gsync();

            // QKV: 3 x 300 tiles merged
            for (int t5 = blockIdx.x; t5 < 900; t5 += nb) {
                int which = t5 / 300, s = t5 % 300;
                int bm = (s / 12) * 32, bn = (s % 12) * 32;
                if (which == 0)
                    gemm_tile32<0>(&sm, g_xn, Wq_l, DMODEL, DMODEL, bm, bn, qs, qb2, g_mq + memD, g_q, 0);
                else if (which == 1)
                    gemm_tile32<0>(&sm, g_xn, Wk_l, DMODEL, DMODEL, bm, bn, ks, kb2, g_mk + memD, g_k, 0);
                else
                    gemm_tile32<0>(&sm, g_xn, Wv_l, DMODEL, DMODEL, bm, bn, vs, vb2, g_mv + memD, g_v, 0);
            }
            gsync();

            // attention: exact integer counts + rounded serial-m einsum2
            for (int item = blockIdx.x; item < 7*32; item += nb) {
                int chunk = item % 7;
                int bh = item / 7;
                int b = bh >> 3, h = bh & 7;
                int n0 = chunk * NCHUNK;
                __syncthreads();
                for (int tt = tid; tt < NTOK*2 + NCHUNK; tt += 256) {
                    int which, n;
                    if (tt < NTOK)        { which = 1; n = tt; }
                    else if (tt < 2*NTOK) { which = 2; n = tt - NTOK; }
                    else                  { which = 0; n = n0 + (tt - 2*NTOK); }
                    const float* src = (which == 0 ? g_q : (which == 1 ? g_k : g_v))
                                       + ((size_t)(b*NTOK + n))*DMODEL + h*HD;
                    unsigned long long bits = 0ull;
                    #pragma unroll
                    for (int j = 0; j < HD; j++)
                        if (src[j] != 0.f) bits |= (1ull << j);
                    if (which == 0)      sm.a.qcb[n - n0] = bits;
                    else if (which == 1) sm.a.kbv[n] = bits;
                    else                 sm.a.vbv[n] = bits;
                }
                __syncthreads();
                for (int idx = tid; idx < NCHUNK*NTOK; idx += 256)
                    sm.a.at[idx/NTOK][idx%NTOK] =
                        (unsigned char)__popcll(sm.a.qcb[idx/NTOK] & sm.a.kbv[idx%NTOK]);
                __syncthreads();
                for (int it2 = tid; it2 < NCHUNK*HD; it2 += 256) {
                    int n = it2 / HD, d = it2 % HD;
                    const unsigned char* arow = sm.a.at[n];
                    float acc = 0.f;
                    for (int m = 0; m < NTOK; m++) {
                        float a = __fmul_rn((float)arow[m], SCALEF);
                        float vm = (float)((sm.a.vbv[m] >> d) & 1ull);
                        acc = __fmaf_rn(a, vm, acc);
                    }
                    g_o[((size_t)(b*NTOK + n0 + n))*DMODEL + h*HD + d] = acc;
                }
                __syncthreads();
            }
            gsync();

            // Wo residual: 300 tiles
            for (int t5 = blockIdx.x; t5 < 300; t5 += nb) {
                int bm = (t5 / 12) * 32, bn = (t5 % 12) * 32;
                gemm_tile32<1>(&sm, g_o, Wo_l, DMODEL, DMODEL, bm, bn, 0, 0, 0, 0, g_y);
            }
            gsync();

            // LN2
            for (int row = blockIdx.x*8 + wrp; row < ROWS; row += nb*8)
                ln_row_warp(g_y + (size_t)row*DMODEL, ln2_g + l*DMODEL, ln2_b + l*DMODEL,
                            g_xn + (size_t)row*DMODEL);
            gsync();

            // MLP1: 25x48 = 1200 tiles
            for (int t5 = blockIdx.x; t5 < 1200; t5 += nb) {
                int bm = (t5 / 48) * 32, bn = (t5 % 48) * 32;
                gemm_tile32<0>(&sm, g_xn, W1_l, MLPD, DMODEL, bm, bn, m1s, m1b, g_m1 + memM, g_s1, 0);
            }
            gsync();

            // MLP2: 300 tiles, K=1536
            for (int t5 = blockIdx.x; t5 < 300; t5 += nb) {
                int bm = (t5 / 12) * 32, bn = (t5 % 12) * 32;
                gemm_tile32<2>(&sm, g_s1, W2_l, DMODEL, MLPD, bm, bn, m2s, m2b, g_m2 + memD, 0, g_y);
            }
            gsync();
        }

        // final LN
        for (int row = blockIdx.x*8 + wrp; row < ROWS; row += nb*8)
            ln_row_warp(g_y + (size_t)row*DMODEL, lnf_g, lnf_b, g_xn + (size_t)row*DMODEL);
        gsync();

        // token-mean pool (serial over n, ascending — major-dim reduce order)
        for (int it = gtid; it < BSZ*DMODEL; it += nth) {
            int b = it / DMODEL, d = it % DMODEL;
            float acc = 0.f;
            for (int n = 0; n < NTOK; n++)
                acc = __fadd_rn(acc, g_xn[((size_t)(b*NTOK + n))*DMODEL + d]);
            g_pool[it] = __fdiv_rn(acc, 196.0f);
        }
        gsync();

        // head logits + LIF (block 0): Eigen serial-k FMA
        if (blockIdx.x == 0 && tid < BSZ*NCLS) {
            int b = tid / NCLS, c = tid % NCLS;
            float acc = 0.f;
            for (int d = 0; d < DMODEL; d++)
                acc = __fmaf_rn(g_pool[b*DMODEL + d], head_w[d*NCLS + c], acc);
            float inp = __fadd_rn(acc, head_b[c]);
            float mm = __fadd_rn(__fmul_rn(BETAF, g_mh[tid]), inp);
            float s = (mm > 1.0f) ? 1.0f : 0.0f;
            g_mh[tid] = __fadd_rn(mm, -s);
            g_acc[tid] += s;
        }
        gsync();
    }

    if (blockIdx.x == 0 && tid < BSZ*NCLS)
        out[tid] = __fdiv_rn(g_acc[tid], (float)TSTEPS);
}

// ---------------- host ----------------
extern "C" void kernel_launch(void* const* d_in, const int* in_sizes, int n_in,
                              void* d_out, int out_size)
{
    const float* x       = (const float*)d_in[0];
    const float* conv_w  = (const float*)d_in[1];
    const float* bn0_s   = (const float*)d_in[2];
    const float* bn0_b   = (const float*)d_in[3];
    const float* pos     = (const float*)d_in[4];
    const float* Wq      = (const float*)d_in[5];
    const float* bnq_s   = (const float*)d_in[6];
    const float* bnq_b   = (const float*)d_in[7];
    const float* Wk      = (const float*)d_in[8];
    const float* bnk_s   = (const float*)d_in[9];
    const float* bnk_b   = (const float*)d_in[10];
    const float* Wv      = (const float*)d_in[11];
    const float* bnv_s   = (const float*)d_in[12];
    const float* bnv_b   = (const float*)d_in[13];
    const float* Wo      = (const float*)d_in[14];
    const float* ln1_g   = (const float*)d_in[15];
    const float* ln1_b   = (const float*)d_in[16];
    const float* W1      = (const float*)d_in[17];
    const float* bn1_s   = (const float*)d_in[18];
    const float* bn1_b   = (const float*)d_in[19];
    const float* W2      = (const float*)d_in[20];
    const float* bn2_s   = (const float*)d_in[21];
    const float* bn2_b   = (const float*)d_in[22];
    const float* ln2_g   = (const float*)d_in[23];
    const float* ln2_b   = (const float*)d_in[24];
    const float* lnf_g   = (const float*)d_in[25];
    const float* lnf_b   = (const float*)d_in[26];
    const float* head_w  = (const float*)d_in[27];
    const float* head_b  = (const float*)d_in[28];
    float* out = (float*)d_out;

    int dev = 0;
    cudaGetDevice(&dev);
    int nsm = 0;
    cudaDeviceGetAttribute(&nsm, cudaDevAttrMultiProcessorCount, dev);
    int bpm = 0;
    cudaOccupancyMaxActiveBlocksPerMultiprocessor(&bpm, mega, 256, 0);
    if (bpm < 1) bpm = 1;
    if (bpm > 3) bpm = 3;
    int nblk = nsm * bpm;

    mega<<<nblk, 256>>>(x, conv_w, bn0_s, bn0_b, pos,
                        Wq, bnq_s, bnq_b, Wk, bnk_s, bnk_b, Wv, bnv_s, bnv_b, Wo,
                        ln1_g, ln1_b, W1, bn1_s, bn1_b, W2, bn2_s, bn2_b,
                        ln2_g, ln2_b, lnf_g, lnf_b, head_w, head_b, out);
}

// round 7
// speedup vs baseline: 1.2347x; 1.2347x over previous
#include <cuda_runtime.h>
#include <math.h>

// ---------------- problem constants ----------------
#define BSZ    4
#define CIN    3
#define IMG    224
#define PATCH  16
#define DMODEL 384
#define DEPTH  4
#define NHEAD  8
#define HD     48
#define MLPD   1536
#define NCLS   5
#define TSTEPS 25
#define NTOK   196
#define ROWS   (BSZ*NTOK) // 784
#define HP     14
#define BETAF  0.9f
#define EPSF   1e-5f
#define SCALEF 0.14433756729740643f  // 48^-0.5
#define NCHUNK 28                     // 196 = 7*28

// ---------------- device state ----------------
__device__ float g_h   [ROWS*DMODEL];
__device__ float g_y   [ROWS*DMODEL];
__device__ float g_xn  [ROWS*DMODEL];
__device__ float g_q   [ROWS*DMODEL];
__device__ float g_k   [ROWS*DMODEL];
__device__ float g_v   [ROWS*DMODEL];
__device__ float g_o   [ROWS*DMODEL];
__device__ float g_s1  [ROWS*MLPD];
__device__ float g_pool[BSZ*DMODEL];
__device__ float g_mpe [ROWS*DMODEL];
__device__ float g_mq  [DEPTH*ROWS*DMODEL];
__device__ float g_mk  [DEPTH*ROWS*DMODEL];
__device__ float g_mv  [DEPTH*ROWS*DMODEL];
__device__ float g_m1  [DEPTH*ROWS*MLPD];
__device__ float g_m2  [DEPTH*ROWS*DMODEL];
__device__ float g_mh  [BSZ*NCLS];
__device__ float g_acc [BSZ*NCLS];

// software grid barrier state
__device__ unsigned g_arrive;
__device__ unsigned g_gen;

__device__ __forceinline__ void gsync()
{
    __syncthreads();
    if (threadIdx.x == 0) {
        __threadfence();
        unsigned gen = *(volatile unsigned*)&g_gen;
        unsigned nb = gridDim.x;
        if (atomicAdd(&g_arrive, 1u) == nb - 1u) {
            g_arrive = 0u;
            __threadfence();
            *(volatile unsigned*)&g_gen = gen + 1u;
        } else {
            while (*(volatile unsigned*)&g_gen == gen) { __nanosleep(64); }
        }
    }
    __syncthreads();
}

// ---------------- shared memory union ----------------
struct SmemU {
    union {
        float patch[CIN*PATCH*PATCH];                       // conv: 3072 B
        struct { float As[16][64]; float Bs[16][64]; } g;   // gemm: 8192 B
        struct {
            unsigned long long qcb[NCHUNK];
            unsigned long long kbv[NTOK];
            unsigned long long vbv[NTOK];
            unsigned char at[NCHUNK][NTOK];
        } a;                                                // attn: ~8.9 KB
    };
};

// ---------------- gemm 64x64 tile, 4x4 microtile, serial-k FMA chain per output ----------------
// MODE 0: LIF -> spike   MODE 1: yout += acc   MODE 2: LIF -> yout += spike
template<int MODE>
__device__ __forceinline__ void gemm_tile64(SmemU* sm,
        const float* __restrict__ A, const float* __restrict__ W,
        int N, int K, int bm, int bn,
        const float* __restrict__ scale, const float* __restrict__ bias,
        float* __restrict__ mem, float* __restrict__ spk, float* __restrict__ yout)
{
    const int tid = threadIdx.x;     // 256
    const int tx = tid & 15;         // N/4
    const int ty = tid >> 4;         // M/4
    const int lr = tid >> 2;         // 0..63
    const int lk = (tid & 3) << 2;   // 0,4,8,12

    float acc[4][4];
    #pragma unroll
    for (int i = 0; i < 4; i++)
        #pragma unroll
        for (int j = 0; j < 4; j++) acc[i][j] = 0.f;

    for (int k0 = 0; k0 < K; k0 += 16) {
        float4 av = make_float4(0.f, 0.f, 0.f, 0.f);
        int ar = bm + lr;
        if (ar < ROWS) av = *reinterpret_cast<const float4*>(A + (size_t)ar*K + k0 + lk);
        sm->g.As[lk+0][lr] = av.x; sm->g.As[lk+1][lr] = av.y;
        sm->g.As[lk+2][lr] = av.z; sm->g.As[lk+3][lr] = av.w;
        float4 bv = *reinterpret_cast<const float4*>(W + (size_t)(bn+lr)*K + k0 + lk);
        sm->g.Bs[lk+0][lr] = bv.x; sm->g.Bs[lk+1][lr] = bv.y;
        sm->g.Bs[lk+2][lr] = bv.z; sm->g.Bs[lk+3][lr] = bv.w;
        __syncthreads();
        #pragma unroll
        for (int kk = 0; kk < 16; kk++) {   // strictly ascending k; single chain per output
            float4 a = *reinterpret_cast<const float4*>(&sm->g.As[kk][ty*4]);
            float4 b = *reinterpret_cast<const float4*>(&sm->g.Bs[kk][tx*4]);
            acc[0][0]=__fmaf_rn(a.x,b.x,acc[0][0]); acc[0][1]=__fmaf_rn(a.x,b.y,acc[0][1]);
            acc[0][2]=__fmaf_rn(a.x,b.z,acc[0][2]); acc[0][3]=__fmaf_rn(a.x,b.w,acc[0][3]);
            acc[1][0]=__fmaf_rn(a.y,b.x,acc[1][0]); acc[1][1]=__fmaf_rn(a.y,b.y,acc[1][1]);
            acc[1][2]=__fmaf_rn(a.y,b.z,acc[1][2]); acc[1][3]=__fmaf_rn(a.y,b.w,acc[1][3]);
            acc[2][0]=__fmaf_rn(a.z,b.x,acc[2][0]); acc[2][1]=__fmaf_rn(a.z,b.y,acc[2][1]);
            acc[2][2]=__fmaf_rn(a.z,b.z,acc[2][2]); acc[2][3]=__fmaf_rn(a.z,b.w,acc[2][3]);
            acc[3][0]=__fmaf_rn(a.w,b.x,acc[3][0]); acc[3][1]=__fmaf_rn(a.w,b.y,acc[3][1]);
            acc[3][2]=__fmaf_rn(a.w,b.z,acc[3][2]); acc[3][3]=__fmaf_rn(a.w,b.w,acc[3][3]);
        }
        __syncthreads();
    }
    #pragma unroll
    for (int i = 0; i < 4; i++) {
        int m = bm + ty*4 + i;
        if (m >= ROWS) break;
        #pragma unroll
        for (int j = 0; j < 4; j++) {
            int n = bn + tx*4 + j;
            size_t idx = (size_t)m*N + n;
            float vv = acc[i][j];
            if (MODE == 1) {
                yout[idx] = __fadd_rn(yout[idx], vv);
            } else {
                vv = __fadd_rn(__fmul_rn(vv, scale[n]), bias[n]);
                float mm = __fadd_rn(__fmul_rn(BETAF, mem[idx]), vv);
                float s = (mm > 1.0f) ? 1.0f : 0.0f;
                mem[idx] = __fadd_rn(mm, -s);
                if (MODE == 0) spk[idx] = s;
                else           yout[idx] = __fadd_rn(yout[idx], s);
            }
        }
    }
}

// ---------------- layernorm row, XLA:CPU vectorized-reduce order ----------------
__device__ __forceinline__ void ln_row_warp(const float* __restrict__ rin,
        const float* __restrict__ g, const float* __restrict__ bta, float* __restrict__ out)
{
    const unsigned fm = 0xffffffffu;
    int lane = threadIdx.x & 31;
    float a = 0.f;
    if (lane < 4) {
        for (int t2 = 0; t2 < 96; t2++) a = __fadd_rn(a, rin[4*t2 + lane]);
    }
    float a0 = __shfl_sync(fm, a, 0), a1 = __shfl_sync(fm, a, 1);
    float a2 = __shfl_sync(fm, a, 2), a3 = __shfl_sync(fm, a, 3);
    float mean = __fdiv_rn(__fadd_rn(__fadd_rn(a0, a2), __fadd_rn(a1, a3)), 384.0f);

    float b = 0.f;
    if (lane < 4) {
        for (int t2 = 0; t2 < 96; t2++) {
            float d = __fadd_rn(rin[4*t2 + lane], -mean);
            b = __fadd_rn(b, __fmul_rn(d, d));
        }
    }
    float b0 = __shfl_sync(fm, b, 0), b1 = __shfl_sync(fm, b, 1);
    float b2 = __shfl_sync(fm, b, 2), b3 = __shfl_sync(fm, b, 3);
    float var = __fdiv_rn(__fadd_rn(__fadd_rn(b0, b2), __fadd_rn(b1, b3)), 384.0f);
    float inv = __fdiv_rn(1.0f, __fsqrt_rn(__fadd_rn(var, EPSF)));

    for (int d = lane; d < DMODEL; d += 32) {
        float dv = __fadd_rn(rin[d], -mean);
        out[d] = __fadd_rn(__fmul_rn(__fmul_rn(dv, inv), g[d]), bta[d]);
    }
}

// ---------------- zero helper ----------------
__device__ __forceinline__ void zero_arr(float* p, int n, int gtid, int nth)
{
    for (int i = gtid; i < n; i += nth) p[i] = 0.f;
}

// ---------------- the megakernel ----------------
__global__ void __launch_bounds__(256, 2) mega(
    const float* __restrict__ x,      const float* __restrict__ conv_w,
    const float* __restrict__ bn0_s,  const float* __restrict__ bn0_b,
    const float* __restrict__ pos,
    const float* __restrict__ Wq,     const float* __restrict__ bnq_s, const float* __restrict__ bnq_b,
    const float* __restrict__ Wk,     const float* __restrict__ bnk_s, const float* __restrict__ bnk_b,
    const float* __restrict__ Wv,     const float* __restrict__ bnv_s, const float* __restrict__ bnv_b,
    const float* __restrict__ Wo,
    const float* __restrict__ ln1_g,  const float* __restrict__ ln1_b,
    const float* __restrict__ W1,     const float* __restrict__ bn1_s, const float* __restrict__ bn1_b,
    const float* __restrict__ W2,     const float* __restrict__ bn2_s, const float* __restrict__ bn2_b,
    const float* __restrict__ ln2_g,  const float* __restrict__ ln2_b,
    const float* __restrict__ lnf_g,  const float* __restrict__ lnf_b,
    const float* __restrict__ head_w, const float* __restrict__ head_b,
    float* __restrict__ out)
{
    __shared__ SmemU sm;
    const int nb  = gridDim.x;
    const int tid = threadIdx.x;
    const int wrp = tid >> 5;
    const int gtid = blockIdx.x * 256 + tid;
    const int nth  = nb * 256;

    // ---- zero persistent state ----
    zero_arr(g_mpe, ROWS*DMODEL, gtid, nth);
    zero_arr(g_mq,  DEPTH*ROWS*DMODEL, gtid, nth);
    zero_arr(g_mk,  DEPTH*ROWS*DMODEL, gtid, nth);
    zero_arr(g_mv,  DEPTH*ROWS*DMODEL, gtid, nth);
    zero_arr(g_m1,  DEPTH*ROWS*MLPD, gtid, nth);
    zero_arr(g_m2,  DEPTH*ROWS*DMODEL, gtid, nth);
    zero_arr(g_mh,  BSZ*NCLS, gtid, nth);
    zero_arr(g_acc, BSZ*NCLS, gtid, nth);

    // ---- conv patch embed (timestep-invariant); Eigen tap order (kh, kw, c), c minor ----
    for (int item = blockIdx.x; item < ROWS; item += nb) {
        int b = item / NTOK, n = item % NTOK;
        int py = n / HP, px = n % HP;
        for (int idx = tid; idx < 768; idx += 256) {
            int c = idx >> 8; int rem = idx & 255; int i = rem >> 4; int j = rem & 15;
            sm.patch[idx] = x[(((size_t)b*CIN + c)*IMG + (py*PATCH + i))*IMG + (px*PATCH + j)];
        }
        __syncthreads();
        for (int d = tid; d < DMODEL; d += 256) {
            const float* wr = conv_w + (size_t)d*768;
            float acc = 0.f;
            for (int i = 0; i < PATCH; i++)
                for (int j = 0; j < PATCH; j++)
                    #pragma unroll
                    for (int c = 0; c < CIN; c++) {
                        int off = c*256 + i*16 + j;
                        acc = __fmaf_rn(sm.patch[off], wr[off], acc);
                    }
            g_h[((size_t)b*NTOK + n)*DMODEL + d] = __fadd_rn(__fmul_rn(acc, bn0_s[d]), bn0_b[d]);
        }
        __syncthreads();
    }
    gsync();

    // ---- timestep loop ----
    for (int t = 0; t < TSTEPS; t++) {
        // patch-embed LIF + pos
        for (int i = gtid; i < ROWS*DMODEL; i += nth) {
            float mm = __fadd_rn(__fmul_rn(BETAF, g_mpe[i]), g_h[i]);
            float s = (mm > 1.0f) ? 1.0f : 0.0f;
            g_mpe[i] = __fadd_rn(mm, -s);
            g_y[i] = __fadd_rn(s, pos[i % (NTOK*DMODEL)]);
        }
        gsync();

        for (int l = 0; l < DEPTH; l++) {
            const size_t wOff  = (size_t)l * DMODEL * DMODEL;
            const size_t w1Off = (size_t)l * MLPD * DMODEL;
            const size_t memD  = (size_t)l * ROWS * DMODEL;
            const size_t memM  = (size_t)l * ROWS * MLPD;
            const float* Wq_l = Wq + wOff;   const float* Wk_l = Wk + wOff;
            const float* Wv_l = Wv + wOff;   const float* Wo_l = Wo + wOff;
            const float* W1_l = W1 + w1Off;  const float* W2_l = W2 + w1Off;
            const float* qs = bnq_s + l*DMODEL, *qb2 = bnq_b + l*DMODEL;
            const float* ks = bnk_s + l*DMODEL, *kb2 = bnk_b + l*DMODEL;
            const float* vs = bnv_s + l*DMODEL, *vb2 = bnv_b + l*DMODEL;
            const float* m1s = bn1_s + l*MLPD,  *m1b = bn1_b + l*MLPD;
            const float* m2s = bn2_s + l*DMODEL, *m2b = bn2_b + l*DMODEL;

            // LN1 (warp per row)
            for (int row = blockIdx.x*8 + wrp; row < ROWS; row += nb*8)
                ln_row_warp(g_y + (size_t)row*DMODEL, ln1_g + l*DMODEL, ln1_b + l*DMODEL,
                            g_xn + (size_t)row*DMODEL);
            gsync();

            // QKV: 3 x (13x6)=234 tiles of 64x64
            for (int t5 = blockIdx.x; t5 < 234; t5 += nb) {
                int which = t5 / 78, s = t5 % 78;
                int bm = (s / 6) * 64, bn = (s % 6) * 64;
                if (which == 0)
                    gemm_tile64<0>(&sm, g_xn, Wq_l, DMODEL, DMODEL, bm, bn, qs, qb2, g_mq + memD, g_q, 0);
                else if (which == 1)
                    gemm_tile64<0>(&sm, g_xn, Wk_l, DMODEL, DMODEL, bm, bn, ks, kb2, g_mk + memD, g_k, 0);
                else
                    gemm_tile64<0>(&sm, g_xn, Wv_l, DMODEL, DMODEL, bm, bn, vs, vb2, g_mv + memD, g_v, 0);
            }
            gsync();

            // attention: exact integer counts + rounded serial-m einsum2
            for (int item = blockIdx.x; item < 7*32; item += nb) {
                int chunk = item % 7;
                int bh = item / 7;
                int b = bh >> 3, h = bh & 7;
                int n0 = chunk * NCHUNK;
                __syncthreads();
                for (int tt = tid; tt < NTOK*2 + NCHUNK; tt += 256) {
                    int which, n;
                    if (tt < NTOK)        { which = 1; n = tt; }
                    else if (tt < 2*NTOK) { which = 2; n = tt - NTOK; }
                    else                  { which = 0; n = n0 + (tt - 2*NTOK); }
                    const float* src = (which == 0 ? g_q : (which == 1 ? g_k : g_v))
                                       + ((size_t)(b*NTOK + n))*DMODEL + h*HD;
                    unsigned long long bits = 0ull;
                    #pragma unroll
                    for (int j = 0; j < HD; j++)
                        if (src[j] != 0.f) bits |= (1ull << j);
                    if (which == 0)      sm.a.qcb[n - n0] = bits;
                    else if (which == 1) sm.a.kbv[n] = bits;
                    else                 sm.a.vbv[n] = bits;
                }
                __syncthreads();
                for (int idx = tid; idx < NCHUNK*NTOK; idx += 256)
                    sm.a.at[idx/NTOK][idx%NTOK] =
                        (unsigned char)__popcll(sm.a.qcb[idx/NTOK] & sm.a.kbv[idx%NTOK]);
                __syncthreads();
                for (int it2 = tid; it2 < NCHUNK*HD; it2 += 256) {
                    int n = it2 / HD, d = it2 % HD;
                    const unsigned char* arow = sm.a.at[n];
                    float acc = 0.f;
                    for (int m = 0; m < NTOK; m++) {
                        float a = __fmul_rn((float)arow[m], SCALEF);
                        float vm = (float)((sm.a.vbv[m] >> d) & 1ull);
                        acc = __fmaf_rn(a, vm, acc);
                    }
                    g_o[((size_t)(b*NTOK + n0 + n))*DMODEL + h*HD + d] = acc;
                }
                __syncthreads();
            }
            gsync();

            // Wo residual: 78 tiles
            for (int t5 = blockIdx.x; t5 < 78; t5 += nb) {
                int bm = (t5 / 6) * 64, bn = (t5 % 6) * 64;
                gemm_tile64<1>(&sm, g_o, Wo_l, DMODEL, DMODEL, bm, bn, 0, 0, 0, 0, g_y);
            }
            gsync();

            // LN2
            for (int row = blockIdx.x*8 + wrp; row < ROWS; row += nb*8)
                ln_row_warp(g_y + (size_t)row*DMODEL, ln2_g + l*DMODEL, ln2_b + l*DMODEL,
                            g_xn + (size_t)row*DMODEL);
            gsync();

            // MLP1: 13x24 = 312 tiles
            for (int t5 = blockIdx.x; t5 < 312; t5 += nb) {
                int bm = (t5 / 24) * 64, bn = (t5 % 24) * 64;
                gemm_tile64<0>(&sm, g_xn, W1_l, MLPD, DMODEL, bm, bn, m1s, m1b, g_m1 + memM, g_s1, 0);
            }
            gsync();

            // MLP2: 78 tiles, K=1536
            for (int t5 = blockIdx.x; t5 < 78; t5 += nb) {
                int bm = (t5 / 6) * 64, bn = (t5 % 6) * 64;
                gemm_tile64<2>(&sm, g_s1, W2_l, DMODEL, MLPD, bm, bn, m2s, m2b, g_m2 + memD, 0, g_y);
            }
            gsync();
        }

        // final LN
        for (int row = blockIdx.x*8 + wrp; row < ROWS; row += nb*8)
            ln_row_warp(g_y + (size_t)row*DMODEL, lnf_g, lnf_b, g_xn + (size_t)row*DMODEL);
        gsync();

        // token-mean pool (serial over n, ascending — major-dim reduce order)
        for (int it = gtid; it < BSZ*DMODEL; it += nth) {
            int b = it / DMODEL, d = it % DMODEL;
            float acc = 0.f;
            for (int n = 0; n < NTOK; n++)
                acc = __fadd_rn(acc, g_xn[((size_t)(b*NTOK + n))*DMODEL + d]);
            g_pool[it] = __fdiv_rn(acc, 196.0f);
        }
        gsync();

        // head logits + LIF (block 0): Eigen serial-k FMA
        if (blockIdx.x == 0 && tid < BSZ*NCLS) {
            int b = tid / NCLS, c = tid % NCLS;
            float acc = 0.f;
            for (int d = 0; d < DMODEL; d++)
                acc = __fmaf_rn(g_pool[b*DMODEL + d], head_w[d*NCLS + c], acc);
            float inp = __fadd_rn(acc, head_b[c]);
            float mm = __fadd_rn(__fmul_rn(BETAF, g_mh[tid]), inp);
            float s = (mm > 1.0f) ? 1.0f : 0.0f;
            g_mh[tid] = __fadd_rn(mm, -s);
            g_acc[tid] += s;
        }
        gsync();
    }

    if (blockIdx.x == 0 && tid < BSZ*NCLS)
        out[tid] = __fdiv_rn(g_acc[tid], (float)TSTEPS);
}

// ---------------- host ----------------
extern "C" void kernel_launch(void* const* d_in, const int* in_sizes, int n_in,
                              void* d_out, int out_size)
{
    const float* x       = (const float*)d_in[0];
    const float* conv_w  = (const float*)d_in[1];
    const float* bn0_s   = (const float*)d_in[2];
    const float* bn0_b   = (const float*)d_in[3];
    const float* pos     = (const float*)d_in[4];
    const float* Wq      = (const float*)d_in[5];
    const float* bnq_s   = (const float*)d_in[6];
    const float* bnq_b   = (const float*)d_in[7];
    const float* Wk      = (const float*)d_in[8];
    const float* bnk_s   = (const float*)d_in[9];
    const float* bnk_b   = (const float*)d_in[10];
    const float* Wv      = (const float*)d_in[11];
    const float* bnv_s   = (const float*)d_in[12];
    const float* bnv_b   = (const float*)d_in[13];
    const float* Wo      = (const float*)d_in[14];
    const float* ln1_g   = (const float*)d_in[15];
    const float* ln1_b   = (const float*)d_in[16];
    const float* W1      = (const float*)d_in[17];
    const float* bn1_s   = (const float*)d_in[18];
    const float* bn1_b   = (const float*)d_in[19];
    const float* W2      = (const float*)d_in[20];
    const float* bn2_s   = (const float*)d_in[21];
    const float* bn2_b   = (const float*)d_in[22];
    const float* ln2_g   = (const float*)d_in[23];
    const float* ln2_b   = (const float*)d_in[24];
    const float* lnf_g   = (const float*)d_in[25];
    const float* lnf_b   = (const float*)d_in[26];
    const float* head_w  = (const float*)d_in[27];
    const float* head_b  = (const float*)d_in[28];
    float* out = (float*)d_out;

    int dev = 0;
    cudaGetDevice(&dev);
    int nsm = 0;
    cudaDeviceGetAttribute(&nsm, cudaDevAttrMultiProcessorCount, dev);
    int bpm = 0;
    cudaOccupancyMaxActiveBlocksPerMultiprocessor(&bpm, mega, 256, 0);
    if (bpm < 1) bpm = 1;
    if (bpm > 2) bpm = 2;
    int nblk = nsm * bpm;

    mega<<<nblk, 256>>>(x, conv_w, bn0_s, bn0_b, pos,
                        Wq, bnq_s, bnq_b, Wk, bnk_s, bnk_b, Wv, bnv_s, bnv_b, Wo,
                        ln1_g, ln1_b, W1, bn1_s, bn1_b, W2, bn2_s, bn2_b,
                        ln2_g, ln2_b, lnf_g, lnf_b, head_w, head_b, out);
}